// round 11
// baseline (speedup 1.0000x reference)
#include <cuda_runtime.h>
#include <cuda_bf16.h>
#include <cstdint>

// AbsDiff cost volume:
//   out[n, d, y, x] = |image1[n,0,y,x] - image2[n,0,y,x-d]|  if x-d >= 0 else 0
// in [2,1,384,1248] fp32, out [2,128,384,1248] fp32. HBM-write-bound (~491MB).
// R11 (final probe): 256-bit stores. Thread owns 8 consecutive x; for the 8
// unrolled d's the shifted reads live in a 16-float window (4x LDG.128, 32B
// aligned since x0,d0 are multiples of 8). One st.global.cs.v8.b32 per
// (thread, d): half the store instructions, 8KB contiguous per warp-instr.
// 2*384*156 = 119808 = 468*256 exact.

#define W_DIM    1248
#define H_DIM    384
#define N_DIM    2
#define D_DIM    128
#define W8       (W_DIM / 8)          // 156
#define THREADS  256
#define D_CHUNK  8                    // d0 = 8*blockIdx.y
#define XY_BLKS  ((N_DIM * H_DIM * W8) / THREADS)   // 468, exact

__device__ __forceinline__ void stcs8(void* p, const float* v) {
    asm volatile("st.global.cs.v8.b32 [%0], {%1,%2,%3,%4,%5,%6,%7,%8};"
                 :: "l"(p),
                    "r"(__float_as_uint(v[0])), "r"(__float_as_uint(v[1])),
                    "r"(__float_as_uint(v[2])), "r"(__float_as_uint(v[3])),
                    "r"(__float_as_uint(v[4])), "r"(__float_as_uint(v[5])),
                    "r"(__float_as_uint(v[6])), "r"(__float_as_uint(v[7]))
                 : "memory");
}

__global__ __launch_bounds__(THREADS, 6)
void absdiff_costvol_kernel(const float* __restrict__ left,
                            const float* __restrict__ right,
                            float* __restrict__ out)
{
    // Flat id over (n, y, x8): x8 fastest so warps are x-contiguous.
    const int gid = blockIdx.x * THREADS + threadIdx.x;   // < 119808
    const int x8  = gid % W8;
    const int ny  = gid / W8;                             // n*H + y, < 768
    const int d0  = blockIdx.y * D_CHUNK;                 // multiple of 8

    const int x0 = 8 * x8;

    // Left: 8 floats at x0 (two aligned LDG.128).
    const float4* lrow4 = reinterpret_cast<const float4*>(
                              left + (size_t)ny * W_DIM);
    float Lr[8];
    {
        const float4 A = lrow4[2 * x8];
        const float4 B = lrow4[2 * x8 + 1];
        Lr[0]=A.x; Lr[1]=A.y; Lr[2]=A.z; Lr[3]=A.w;
        Lr[4]=B.x; Lr[5]=B.y; Lr[6]=B.z; Lr[7]=B.w;
    }

    // Window: floats [x0-d0-8, x0-d0+7] of the right row (16 floats, 4x
    // aligned float4). Covers R[x0-d .. x0+7-d] for all d in [d0, d0+7].
    // Negative block indices clamp to 0 — clamped values feed only
    // mask-zeroed outputs (x < d there).
    const float4* rrow4 = reinterpret_cast<const float4*>(
                              right + (size_t)ny * W_DIM);
    const int b  = 2 * x8 - d0 / 4 - 2;   // float4 index of window start
    const int b0 = b     < 0 ? 0 : b;
    const int b1 = b + 1 < 0 ? 0 : b + 1;
    const int b2 = b + 2 < 0 ? 0 : b + 2;
    const int b3 = b + 3 < 0 ? 0 : b + 3;

    float w[16];
    {
        const float4 X = rrow4[b0];
        const float4 Y = rrow4[b1];
        const float4 Z = rrow4[b2];
        const float4 U = rrow4[b3];
        w[0] =X.x; w[1] =X.y; w[2] =X.z; w[3] =X.w;
        w[4] =Y.x; w[5] =Y.y; w[6] =Y.z; w[7] =Y.w;
        w[8] =Z.x; w[9] =Z.y; w[10]=Z.z; w[11]=Z.w;
        w[12]=U.x; w[13]=U.y; w[14]=U.z; w[15]=U.w;
    }

    const int n = ny / H_DIM;
    const int y = ny % H_DIM;
    float* ob = out + ((size_t)(n * D_DIM + d0) * H_DIM + y) * W_DIM + x0;

    #pragma unroll
    for (int k = 0; k < D_CHUNK; ++k) {
        const int d  = d0 + k;
        const int j0 = 8 - k;            // compile-time window offset

        float v[8];
        #pragma unroll
        for (int i = 0; i < 8; ++i)
            v[i] = (x0 + i >= d) ? fabsf(Lr[i] - w[j0 + i]) : 0.f;

        stcs8(ob + (size_t)k * (H_DIM * W_DIM), v);
    }
}

extern "C" void kernel_launch(void* const* d_in, const int* in_sizes, int n_in,
                              void* d_out, int out_size)
{
    const float* image1 = (const float*)d_in[0];  // left
    const float* image2 = (const float*)d_in[1];  // right (shifted source)
    float* out = (float*)d_out;

    (void)in_sizes; (void)n_in; (void)out_size;

    dim3 grid(XY_BLKS, D_DIM / D_CHUNK);   // 468 x 16 = 7488 blocks
    dim3 block(THREADS);
    absdiff_costvol_kernel<<<grid, block>>>(image1, image2, out);
}

// round 12
// speedup vs baseline: 1.1194x; 1.1194x over previous
#include <cuda_runtime.h>
#include <cuda_bf16.h>

// AbsDiff cost volume (FINAL — converged at HBM write ceiling):
//   out[n, d, y, x] = |image1[n,0,y,x] - image2[n,0,y,x-d]|  if x-d >= 0 else 0
// in [2,1,384,1248] fp32, out [2,128,384,1248] fp32. HBM-write-bound: ~491MB
// of stores, 61.4us floor @ 8TB/s spec; this kernel achieves ~68us kernel
// time (~90% effective). Ablated and rejected: occ 4..32, CTA 64..416,
// no-smem LDG windows, D_CHUNK 16, TMA bulk stores, L2 evict_last inputs,
// 256-bit stores — all neutral or regressions; the STG.128 .cs stream at
// occ 6 with D_CHUNK=8 is the optimum.
//
// Structure: one CTA per (n,y,d-chunk-of-8). Right row staged once in smem
// (PAD leading zeros so x-d never underflows). Each thread owns 4 consecutive
// x; all 8 shifted windows for the unrolled d's live in a 12-float span ->
// 3 LDS.128 once, compile-time register selects, 8x STG.128 evict-first.

#define W_DIM    1248
#define H_DIM    384
#define N_DIM    2
#define D_DIM    128
#define W4       (W_DIM / 4)          // 312
#define THREADS  320                  // 10 warps; threads >= W4
#define D_SPLIT  16
#define D_CHUNK  (D_DIM / D_SPLIT)    // 8; d0 is a multiple of 8 (and of 4)
#define PAD      128                  // leading zeros so x-d never underflows

__device__ __forceinline__ void stcs4(float4* p, float4 v) {
    asm volatile("st.global.cs.v4.f32 [%0], {%1,%2,%3,%4};"
                 :: "l"(p), "f"(v.x), "f"(v.y), "f"(v.z), "f"(v.w) : "memory");
}

__global__ __launch_bounds__(THREADS, 6)
void absdiff_costvol_kernel(const float* __restrict__ left,
                            const float* __restrict__ right,
                            float* __restrict__ out)
{
    __shared__ float4 sr4[(PAD + W_DIM) / 4];   // 344 float4 = 5.5 KB

    const int nh = blockIdx.x;                  // n*H + y   (768)
    const int d0 = blockIdx.y * D_CHUNK;        // multiple of 8
    const int t  = threadIdx.x;

    const float4* rrow4 = (const float4*)(right + (size_t)nh * W_DIM);
    const float4* lrow4 = (const float4*)(left  + (size_t)nh * W_DIM);

    // Stage: zeros in the pad, right row after it.
    if (t < PAD / 4)
        sr4[t] = make_float4(0.f, 0.f, 0.f, 0.f);
    float4 L = make_float4(0.f, 0.f, 0.f, 0.f);
    if (t < W4) {
        sr4[PAD / 4 + t] = rrow4[t];
        L = lrow4[t];
    }

    __syncthreads();

    const int n = nh / H_DIM;
    const int y = nh % H_DIM;
    float* ob = out + ((size_t)(n * D_DIM + d0) * H_DIM + y) * W_DIM;

    if (t < W4) {
        const int x0 = 4 * t;                   // first x this thread owns
        const int c0 = PAD - d0 + x0;           // smem float idx of R[x0-d0]; %4==0
        const int b4 = c0 >> 2;                 // >= 2 always (c0 >= 8)

        // One-shot window load: floats [c0-8, c0+3] cover all 8 shifted reads.
        float w[12];
        {
            const float4 X = sr4[b4 - 2];
            const float4 Y = sr4[b4 - 1];
            const float4 Z = sr4[b4];
            w[0]=X.x; w[1]=X.y; w[2]=X.z;  w[3]=X.w;
            w[4]=Y.x; w[5]=Y.y; w[6]=Y.z;  w[7]=Y.w;
            w[8]=Z.x; w[9]=Z.y; w[10]=Z.z; w[11]=Z.w;
        }

        #pragma unroll
        for (int k = 0; k < D_CHUNK; ++k) {
            const int d  = d0 + k;
            const int j0 = 8 - k;               // window start inside w[], const

            float4 v;
            v.x = (x0 + 0 >= d) ? fabsf(L.x - w[j0 + 0]) : 0.f;
            v.y = (x0 + 1 >= d) ? fabsf(L.y - w[j0 + 1]) : 0.f;
            v.z = (x0 + 2 >= d) ? fabsf(L.z - w[j0 + 2]) : 0.f;
            v.w = (x0 + 3 >= d) ? fabsf(L.w - w[j0 + 3]) : 0.f;

            stcs4((float4*)(ob + (size_t)k * (H_DIM * W_DIM)) + t, v);
        }
    }
}

extern "C" void kernel_launch(void* const* d_in, const int* in_sizes, int n_in,
                              void* d_out, int out_size)
{
    const float* image1 = (const float*)d_in[0];  // left
    const float* image2 = (const float*)d_in[1];  // right (shifted source)
    float* out = (float*)d_out;

    (void)in_sizes; (void)n_in; (void)out_size;

    dim3 grid(N_DIM * H_DIM, D_SPLIT);   // 768 x 16 = 12288 blocks
    dim3 block(THREADS);
    absdiff_costvol_kernel<<<grid, block>>>(image1, image2, out);
}

// round 13
// speedup vs baseline: 1.1282x; 1.0079x over previous
#include <cuda_runtime.h>
#include <cuda_bf16.h>

// AbsDiff cost volume:
//   out[n, d, y, x] = |image1[n,0,y,x] - image2[n,0,y,x-d]|  if x-d >= 0 else 0
// in [2,1,384,1248] fp32, out [2,128,384,1248] fp32. HBM-write-bound (~491MB).
// R13: probe store-chain-length curve downward. D_CHUNK 16->71.8us, 8->69.7us;
// test 4 (shorter per-thread store chains = more independent store streams,
// cost = 2x input L2 re-reads, which have headroom). No smem, 256 thr, occ 8.
// Window for 4 unrolled d's = 8 floats = 2 aligned LDG.128.

#define W_DIM    1248
#define H_DIM    384
#define N_DIM    2
#define D_DIM    128
#define W4       (W_DIM / 4)          // 312
#define THREADS  256
#define D_CHUNK  4                    // d0 = 4*blockIdx.y, multiple of 4
#define XY_BLKS  ((N_DIM * H_DIM * W4) / THREADS)   // 936, exact

__device__ __forceinline__ void stcs4(float4* p, float4 v) {
    asm volatile("st.global.cs.v4.f32 [%0], {%1,%2,%3,%4};"
                 :: "l"(p), "f"(v.x), "f"(v.y), "f"(v.z), "f"(v.w) : "memory");
}

__global__ __launch_bounds__(THREADS, 8)
void absdiff_costvol_kernel(const float* __restrict__ left,
                            const float* __restrict__ right,
                            float* __restrict__ out)
{
    // Flat id over (n, y, x4): x4 fastest so warps are x-contiguous.
    const int gid = blockIdx.x * THREADS + threadIdx.x;   // < 239616
    const int x4  = gid % W4;
    const int ny  = gid / W4;                             // n*H + y, < 768
    const int d0  = blockIdx.y * D_CHUNK;                 // multiple of 4

    const int x0 = 4 * x4;

    // Left float4 (always in-bounds, aligned).
    const float4 L = reinterpret_cast<const float4*>(
                         left + (size_t)ny * W_DIM)[x4];

    // Window: floats [x0-d0-4, x0-d0+3] of the right row (blocks b, b+1).
    // Covers R[x0-d .. x0+3-d] for d in [d0, d0+3]. Negative blocks clamp
    // to 0 — clamped values feed only mask-zeroed outputs (x < d there).
    const float4* rrow4 = reinterpret_cast<const float4*>(
                              right + (size_t)ny * W_DIM);
    const int b  = x4 - d0 / 4 - 1;      // may be negative, <= 310
    const int b0 = b     < 0 ? 0 : b;
    const int b1 = b + 1 < 0 ? 0 : b + 1;

    float w[8];
    {
        const float4 X = rrow4[b0];
        const float4 Y = rrow4[b1];
        w[0]=X.x; w[1]=X.y; w[2]=X.z; w[3]=X.w;
        w[4]=Y.x; w[5]=Y.y; w[6]=Y.z; w[7]=Y.w;
    }

    const int n = ny / H_DIM;
    const int y = ny % H_DIM;
    float* ob = out + ((size_t)(n * D_DIM + d0) * H_DIM + y) * W_DIM + x0;

    #pragma unroll
    for (int k = 0; k < D_CHUNK; ++k) {
        const int d  = d0 + k;
        const int j0 = 4 - k;            // compile-time window offset

        float4 v;
        v.x = (x0 + 0 >= d) ? fabsf(L.x - w[j0 + 0]) : 0.f;
        v.y = (x0 + 1 >= d) ? fabsf(L.y - w[j0 + 1]) : 0.f;
        v.z = (x0 + 2 >= d) ? fabsf(L.z - w[j0 + 2]) : 0.f;
        v.w = (x0 + 3 >= d) ? fabsf(L.w - w[j0 + 3]) : 0.f;

        stcs4((float4*)(ob + (size_t)k * (H_DIM * W_DIM)), v);
    }
}

extern "C" void kernel_launch(void* const* d_in, const int* in_sizes, int n_in,
                              void* d_out, int out_size)
{
    const float* image1 = (const float*)d_in[0];  // left
    const float* image2 = (const float*)d_in[1];  // right (shifted source)
    float* out = (float*)d_out;

    (void)in_sizes; (void)n_in; (void)out_size;

    dim3 grid(XY_BLKS, D_DIM / D_CHUNK);   // 936 x 32 = 29952 blocks
    dim3 block(THREADS);
    absdiff_costvol_kernel<<<grid, block>>>(image1, image2, out);
}